// round 16
// baseline (speedup 1.0000x reference)
#include <cuda_runtime.h>
#include <cstdint>
#include <math.h>

#define DIV_UP(a,b) (((a)+(b)-1)/(b))

// Problem constants
constexpr int cB   = 16;
constexpr int cT   = 24;
constexpr int cN   = 500;
constexpr int cF   = 2;
constexpr int cH   = 64;
constexpr int cD   = 8;
constexpr int cTGN = 32;
constexpr int cHYP = 16;
constexpr int cLEN = 24;
constexpr int cB4  = cB * 4;

constexpr float kAL = 0.05f, kBE = 0.95f, kGA = 0.95f, kTAU = 2.0f;

// padded chain layout: 3 slices of 72 floats each, row stride 216
constexpr int CP   = 72;
constexpr int LDCH = 216;

// dual-gconv dynamic smem: 4 coef arrays x 2 stages + h x 2 stages
constexpr int GD_CF = 32 * 36 * 4;    // 4608 per coef tile
constexpr int GD_HS = 32 * 76 * 4;    // 9728 per h tile
constexpr int GD_SMEM = 8 * GD_CF + 2 * GD_HS;  // 56320

// ---------------- scratch ----------------
__device__ float g_chainS[cB * cN * LDCH];   // slice0 = hidden (persistent per call)
__device__ float g_chainZ[cB * cN * LDCH];
__device__ float g_chainC[cB * cN * LDCH];
__device__ uint32_t g_coefHi[(size_t)cB * cN * cN];
__device__ uint32_t g_coefLo[(size_t)cB * cN * cN];
__device__ float g_adjS[cN * cN];            // adj @ adj
__device__ uint32_t g_C1Hi[cN * cN];
__device__ uint32_t g_C1Lo[cN * cN];
__device__ uint32_t g_C2Hi[cN * cN];
__device__ uint32_t g_C2Lo[cN * cN];
__device__ float g_ns[cB * cN * cHYP];
__device__ float g_nt[cB * cN * cHYP];
__device__ float g_z[cB * cN * cH];
__device__ float g_Atgn[(size_t)cB4 * cN * cN];
__device__ float g_q[cB * cN * cD];
__device__ float g_k[cB4 * cN * cD];
__device__ float g_chainT[cB4 * cN * 6];
__device__ float g_tar2[cB * cN * cTGN];
__device__ float g_gat[cB * cN * cF];

// side stream + fork/join events, created ONCE at program load.
struct SideStream {
    cudaStream_t s = nullptr;
    cudaEvent_t fork = nullptr, join = nullptr;
    SideStream() {
        cudaStreamCreateWithFlags(&s, cudaStreamNonBlocking);
        cudaEventCreateWithFlags(&fork, cudaEventDisableTiming);
        cudaEventCreateWithFlags(&join, cudaEventDisableTiming);
    }
};
static SideStream g_ss;

__device__ __forceinline__ float tanh_fast(float x) {
    float y;
    asm("tanh.approx.f32 %0, %1;" : "=f"(y) : "f"(x));
    return y;
}
__device__ __forceinline__ float sigmoid_fast(float x) {
    return 1.f / (1.f + __expf(-x));
}
__device__ __forceinline__ void cp_async16(uint32_t saddr, const void* gptr, int psize) {
    asm volatile("cp.async.ca.shared.global [%0], [%1], 16, %2;\n"
                 :: "r"(saddr), "l"(gptr), "r"(psize));
}
__device__ __forceinline__ void cp_commit() {
    asm volatile("cp.async.commit_group;\n");
}
template <int N>
__device__ __forceinline__ void cp_wait() {
    asm volatile("cp.async.wait_group %0;\n" :: "n"(N));
}
__device__ __forceinline__ uint32_t f2tf(float x) {
    uint32_t r;
    asm("cvt.rna.tf32.f32 %0, %1;" : "=r"(r) : "f"(x));
    return r;
}
__device__ __forceinline__ void mma_tf32(float* c,
    uint32_t a0, uint32_t a1, uint32_t a2, uint32_t a3,
    uint32_t b0, uint32_t b1)
{
    asm volatile(
        "mma.sync.aligned.m16n8k8.row.col.f32.tf32.tf32.f32 "
        "{%0,%1,%2,%3}, {%4,%5,%6,%7}, {%8,%9}, {%0,%1,%2,%3};"
        : "+f"(c[0]), "+f"(c[1]), "+f"(c[2]), "+f"(c[3])
        : "r"(a0), "r"(a1), "r"(a2), "r"(a3), "r"(b0), "r"(b1));
}

// ---------------- kernels ----------------

__global__ void k_zero(float* p, int ntot) {
    int i = blockIdx.x * blockDim.x + threadIdx.x;
    if (i < ntot) p[i] = 0.f;
}

// S = adj @ adj (row-major), 32x32 tiled fp32
__global__ __launch_bounds__(1024) void k_adj2(
    const float* __restrict__ adj, float* __restrict__ S, int n)
{
    int tx = threadIdx.x, ty = threadIdx.y;
    int w = blockIdx.x * 32 + tx;
    int u = blockIdx.y * 32 + ty;
    __shared__ float As[32][33];
    __shared__ float Bs[32][33];
    float acc = 0.f;
    for (int v0 = 0; v0 < n; v0 += 32) {
        int va = v0 + tx, vb = v0 + ty;
        As[ty][tx] = (u < n && va < n) ? adj[(size_t)u * n + va] : 0.f;
        Bs[ty][tx] = (vb < n && w < n) ? adj[(size_t)vb * n + w] : 0.f;
        __syncthreads();
#pragma unroll
        for (int k = 0; k < 32; k++)
            acc = fmaf(As[ty][k], Bs[k][tx], acc);
        __syncthreads();
    }
    if (u < n && w < n) S[(size_t)u * n + w] = acc;
}

// C1 = GA*adj + AL*I ; C2 = AL*I + GA*AL*adj + GA^2*(adj@adj) ; emit tf32 hi/lo
__global__ void k_coefhl2(const float* __restrict__ adj, const float* __restrict__ S,
                          uint32_t* __restrict__ c1h, uint32_t* __restrict__ c1l,
                          uint32_t* __restrict__ c2h, uint32_t* __restrict__ c2l, int n)
{
    int i = blockIdx.x * blockDim.x + threadIdx.x;
    if (i >= n * n) return;
    bool diag = (i / n) == (i % n);
    float a = adj[i];
    float v1 = kGA * a + (diag ? kAL : 0.f);
    float v2 = (diag ? kAL : 0.f) + kGA * kAL * a + kGA * kGA * S[i];
    uint32_t h1 = f2tf(v1);
    c1h[i] = h1; c1l[i] = f2tf(v1 - __uint_as_float(h1));
    uint32_t h2 = f2tf(v2);
    c2h[i] = h2; c2l[i] = f2tf(v2 - __uint_as_float(h2));
}

// Dual-output tensor-core graph conv for the S-chain (3xTF32, AL folded into coefs):
//   slice1[w,c] = sum_v C1[v,w]*h[v,c] ; slice2[w,c] = sum_v C2[v,w]*h[v,c]
// PDL-aware: trigger at start, coef prefetch before grid-dependency sync,
// h loads (which read the predecessor's output) after it.
__global__ __launch_bounds__(192) void k_gconv2dual(
    float* __restrict__ buf, int C,
    const uint32_t* __restrict__ A1hi, const uint32_t* __restrict__ A1lo,
    const uint32_t* __restrict__ A2hi, const uint32_t* __restrict__ A2lo, int n)
{
    cudaTriggerProgrammaticLaunchCompletion();

    extern __shared__ char sm[];
    const uint32_t smbase = (uint32_t)__cvta_generic_to_shared(sm);

    const int b  = blockIdx.y;
    const int w0 = blockIdx.x * 32;
    const int tid = threadIdx.x;
    const int lane = tid & 31;
    const int warp = tid >> 5;
    const int wb = (warp & 1) * 16;
    const int cb = (warp >> 1) * 24;
    const int lq = lane >> 2;
    const int lr = lane & 3;

    float acc1[3][4], acc2[3][4];
#pragma unroll
    for (int i = 0; i < 3; i++)
#pragma unroll
        for (int j = 0; j < 4; j++) { acc1[i][j] = 0.f; acc2[i][j] = 0.f; }

    const float* hb = buf + (size_t)b * n * LDCH;   // slice0
    const uint32_t* srcs[4] = {A1hi, A1lo, A2hi, A2lo};

    const int ntiles = DIV_UP(n, 32);

    auto load_coef = [&](int t, int stage) {
        int v0 = t * 32;
#pragma unroll
        for (int it = 0; it < 6; it++) {
            int idx = tid + it * 192;
            if (idx < 1024) {
                int arr = idx >> 8, rem = idx & 255;
                int vi = rem >> 3, seg = rem & 7;
                int v = v0 + vi, w = w0 + seg * 4;
                bool ok = (v < n) && (w < n);
                size_t off = (size_t)(ok ? v : 0) * n + (ok ? w : 0);
                uint32_t dst = smbase + arr * 2 * GD_CF + stage * GD_CF
                             + (vi * 36 + seg * 4) * 4;
                cp_async16(dst, srcs[arr] + off, ok ? 16 : 0);
            }
        }
    };
    auto load_h = [&](int t, int stage) {
        int v0 = t * 32;
#pragma unroll
        for (int it = 0; it < 3; it++) {
            int idx = tid + it * 192;
            int vi = idx / 18, seg = idx % 18;
            int v = v0 + vi;
            bool ok = (v < n);
            uint32_t dst = smbase + 8 * GD_CF + stage * GD_HS + (vi * 76 + seg * 4) * 4;
            cp_async16(dst, hb + (size_t)(ok ? v : 0) * LDCH + seg * 4, ok ? 16 : 0);
        }
    };

    // coef prefetch (written far upstream; safe pre-dependency)
    load_coef(0, 0);
    load_coef(1, 1);
    cp_commit();

    cudaGridDependencySynchronize();

    load_h(0, 0);
    load_h(1, 1);
    cp_commit();

    for (int t = 0; t < ntiles; t++) {
        int cur = t & 1;
        if (t >= 1 && t + 1 < ntiles) {
            load_coef(t + 1, (t + 1) & 1);
            load_h(t + 1, (t + 1) & 1);
            cp_commit();
            cp_wait<1>();
        } else {
            cp_wait<0>();
        }
        __syncthreads();

        const uint32_t (*h1)[36] = (const uint32_t(*)[36])(sm + 0 * GD_CF + cur * GD_CF);
        const uint32_t (*l1)[36] = (const uint32_t(*)[36])(sm + 2 * GD_CF + cur * GD_CF);
        const uint32_t (*h2)[36] = (const uint32_t(*)[36])(sm + 4 * GD_CF + cur * GD_CF);
        const uint32_t (*l2)[36] = (const uint32_t(*)[36])(sm + 6 * GD_CF + cur * GD_CF);
        const float (*hsc)[76]   = (const float(*)[76])(sm + 8 * GD_CF + cur * GD_HS);

#pragma unroll
        for (int k8 = 0; k8 < 4; k8++) {
            int kb = k8 * 8;
            uint32_t a1h0 = h1[kb + lr][wb + lq];
            uint32_t a1h1 = h1[kb + lr][wb + lq + 8];
            uint32_t a1h2 = h1[kb + lr + 4][wb + lq];
            uint32_t a1h3 = h1[kb + lr + 4][wb + lq + 8];
            uint32_t a1l0 = l1[kb + lr][wb + lq];
            uint32_t a1l1 = l1[kb + lr][wb + lq + 8];
            uint32_t a1l2 = l1[kb + lr + 4][wb + lq];
            uint32_t a1l3 = l1[kb + lr + 4][wb + lq + 8];
            uint32_t a2h0 = h2[kb + lr][wb + lq];
            uint32_t a2h1 = h2[kb + lr][wb + lq + 8];
            uint32_t a2h2 = h2[kb + lr + 4][wb + lq];
            uint32_t a2h3 = h2[kb + lr + 4][wb + lq + 8];
            uint32_t a2l0 = l2[kb + lr][wb + lq];
            uint32_t a2l1 = l2[kb + lr][wb + lq + 8];
            uint32_t a2l2 = l2[kb + lr + 4][wb + lq];
            uint32_t a2l3 = l2[kb + lr + 4][wb + lq + 8];

#pragma unroll
            for (int ct = 0; ct < 3; ct++) {
                float br0 = hsc[kb + lr][cb + ct * 8 + lq];
                float br1 = hsc[kb + lr + 4][cb + ct * 8 + lq];
                uint32_t bh0 = f2tf(br0), bh1 = f2tf(br1);
                uint32_t bl0 = f2tf(br0 - __uint_as_float(bh0));
                uint32_t bl1 = f2tf(br1 - __uint_as_float(bh1));

                mma_tf32(acc1[ct], a1h0, a1h1, a1h2, a1h3, bh0, bh1);
                mma_tf32(acc1[ct], a1l0, a1l1, a1l2, a1l3, bh0, bh1);
                mma_tf32(acc1[ct], a1h0, a1h1, a1h2, a1h3, bl0, bl1);
                mma_tf32(acc2[ct], a2h0, a2h1, a2h2, a2h3, bh0, bh1);
                mma_tf32(acc2[ct], a2l0, a2l1, a2l2, a2l3, bh0, bh1);
                mma_tf32(acc2[ct], a2h0, a2h1, a2h2, a2h3, bl0, bl1);
            }
        }
        __syncthreads();
    }

    int wr0 = w0 + wb + lq;
    int wr1 = wr0 + 8;
#pragma unroll
    for (int ct = 0; ct < 3; ct++) {
        int c = cb + ct * 8 + lr * 2;
        if (wr0 < n) {
            float* op = buf + ((size_t)b * n + wr0) * LDCH;
            if (c < C)     { op[CP + c]     = acc1[ct][0]; op[2 * CP + c]     = acc2[ct][0]; }
            if (c + 1 < C) { op[CP + c + 1] = acc1[ct][1]; op[2 * CP + c + 1] = acc2[ct][1]; }
        }
        if (wr1 < n) {
            float* op = buf + ((size_t)b * n + wr1) * LDCH;
            if (c < C)     { op[CP + c]     = acc1[ct][2]; op[2 * CP + c]     = acc2[ct][2]; }
            if (c + 1 < C) { op[CP + c + 1] = acc1[ct][3]; op[2 * CP + c + 1] = acc2[ct][3]; }
        }
    }
}

// Tensor-core graph conv (3xTF32, A pre-split hi/lo), PDL-aware:
// trigger at start; coef prefetch pre-sync; h loads post-sync.
// out[w, sOut*CP+c] = AL*buf[w,c] + sum_v Asplit[b,v,w] * buf[v, sIn*CP+c]
__global__ __launch_bounds__(192) void k_gconv2(
    float* __restrict__ buf, int C, int sIn, int sOut,
    const uint32_t* __restrict__ Ahi, const uint32_t* __restrict__ Alo,
    size_t Abs, int n)
{
    cudaTriggerProgrammaticLaunchCompletion();

    const int b  = blockIdx.y;
    const int w0 = blockIdx.x * 32;
    const int tid = threadIdx.x;
    const int lane = tid & 31;
    const int warp = tid >> 5;
    const int wb = (warp & 1) * 16;
    const int cb = (warp >> 1) * 24;
    const int lq = lane >> 2;
    const int lr = lane & 3;

    __shared__ uint32_t cfh[2][32][36];
    __shared__ uint32_t cfl[2][32][36];
    __shared__ float hs[2][32][76];

    float acc[3][4];
#pragma unroll
    for (int i = 0; i < 3; i++)
#pragma unroll
        for (int j = 0; j < 4; j++) acc[i][j] = 0.f;

    const uint32_t* AhiB = Ahi + (size_t)b * Abs;
    const uint32_t* AloB = Alo + (size_t)b * Abs;
    const float* hb = buf + (size_t)b * n * LDCH + sIn * CP;

    const int ntiles = DIV_UP(n, 32);

    auto load_coef = [&](int t, int stage) {
        int v0 = t * 32;
#pragma unroll
        for (int it = 0; it < 2; it++) {
            int idx = tid + it * 192;
            if (idx < 256) {
                int vi = idx >> 3, seg = idx & 7;
                int v = v0 + vi, w = w0 + seg * 4;
                bool ok = (v < n) && (w < n);
                size_t off = (size_t)(ok ? v : 0) * n + (ok ? w : 0);
                uint32_t dh = (uint32_t)__cvta_generic_to_shared(&cfh[stage][vi][seg * 4]);
                uint32_t dl = (uint32_t)__cvta_generic_to_shared(&cfl[stage][vi][seg * 4]);
                cp_async16(dh, AhiB + off, ok ? 16 : 0);
                cp_async16(dl, AloB + off, ok ? 16 : 0);
            }
        }
    };
    auto load_h = [&](int t, int stage) {
        int v0 = t * 32;
#pragma unroll
        for (int it = 0; it < 3; it++) {
            int idx = tid + it * 192;
            int vi = idx / 18, seg = idx % 18;
            int v = v0 + vi;
            bool ok = (v < n);
            const float* src = hb + (size_t)(ok ? v : 0) * LDCH + seg * 4;
            uint32_t dst = (uint32_t)__cvta_generic_to_shared(&hs[stage][vi][seg * 4]);
            cp_async16(dst, src, ok ? 16 : 0);
        }
    };

    // coef prefetch (written >=2 kernels upstream for all PDL'd launches)
    load_coef(0, 0);
    load_coef(1, 1);
    cp_commit();

    cudaGridDependencySynchronize();

    load_h(0, 0);
    load_h(1, 1);
    cp_commit();

    for (int t = 0; t < ntiles; t++) {
        int cur = t & 1;
        if (t >= 1 && t + 1 < ntiles) {
            load_coef(t + 1, (t + 1) & 1);
            load_h(t + 1, (t + 1) & 1);
            cp_commit();
            cp_wait<1>();
        } else {
            cp_wait<0>();
        }
        __syncthreads();

        const uint32_t (*ch)[36] = cfh[cur];
        const uint32_t (*cl)[36] = cfl[cur];
        const float (*hsc)[76] = hs[cur];

#pragma unroll
        for (int k8 = 0; k8 < 4; k8++) {
            int kb = k8 * 8;
            uint32_t ah0 = ch[kb + lr][wb + lq];
            uint32_t ah1 = ch[kb + lr][wb + lq + 8];
            uint32_t ah2 = ch[kb + lr + 4][wb + lq];
            uint32_t ah3 = ch[kb + lr + 4][wb + lq + 8];
            uint32_t al0 = cl[kb + lr][wb + lq];
            uint32_t al1 = cl[kb + lr][wb + lq + 8];
            uint32_t al2 = cl[kb + lr + 4][wb + lq];
            uint32_t al3 = cl[kb + lr + 4][wb + lq + 8];

#pragma unroll
            for (int ct = 0; ct < 3; ct++) {
                float br0 = hsc[kb + lr][cb + ct * 8 + lq];
                float br1 = hsc[kb + lr + 4][cb + ct * 8 + lq];
                uint32_t bh0 = f2tf(br0), bh1 = f2tf(br1);
                uint32_t bl0 = f2tf(br0 - __uint_as_float(bh0));
                uint32_t bl1 = f2tf(br1 - __uint_as_float(bh1));

                mma_tf32(acc[ct], ah0, ah1, ah2, ah3, bh0, bh1);
                mma_tf32(acc[ct], al0, al1, al2, al3, bh0, bh1);
                mma_tf32(acc[ct], ah0, ah1, ah2, ah3, bl0, bl1);
            }
        }
        __syncthreads();
    }

    int wr0 = w0 + wb + lq;
    int wr1 = wr0 + 8;
#pragma unroll
    for (int ct = 0; ct < 3; ct++) {
        int c = cb + ct * 8 + lr * 2;
        if (wr0 < n) {
            float* op = buf + ((size_t)b * n + wr0) * LDCH;
            if (c < C)     op[sOut * CP + c]     = kAL * op[c]     + acc[ct][0];
            if (c + 1 < C) op[sOut * CP + c + 1] = kAL * op[c + 1] + acc[ct][1];
        }
        if (wr1 < n) {
            float* op = buf + ((size_t)b * n + wr1) * LDCH;
            if (c < C)     op[sOut * CP + c]     = kAL * op[c]     + acc[ct][2];
            if (c + 1 < C) op[sOut * CP + c + 1] = kAL * op[c + 1] + acc[ct][3];
        }
    }
}

// C=2 graph conv for the TGN path (A already includes GA scaling)
__global__ __launch_bounds__(128) void k_gconv_f2(
    float* __restrict__ buf, int sIn, int sOut,
    const float* __restrict__ A, int n)
{
    int bt = blockIdx.y;
    int w0 = blockIdx.x * 128;
    int tid = threadIdx.x;
    __shared__ float As[2][32][132];
    __shared__ float2 xs[2][32];
    float a0 = 0.f, a1 = 0.f;
    const float* Ab = A + (size_t)bt * n * n;
    const float* hb = buf + (size_t)bt * n * 6 + sIn * 2;

    const int ntiles = DIV_UP(n, 32);

    auto load_tile = [&](int t, int stage) {
        int v0 = t * 32;
#pragma unroll
        for (int it = 0; it < 8; it++) {
            int idx = tid + it * 128;
            int vi = idx >> 5, seg = idx & 31;
            int v = v0 + vi, w = w0 + seg * 4;
            bool ok = (v < n) && (w < n);
            const float* src = Ab + (size_t)(ok ? v : 0) * n + (ok ? w : 0);
            uint32_t dst = (uint32_t)__cvta_generic_to_shared(&As[stage][vi][seg * 4]);
            cp_async16(dst, src, ok ? 16 : 0);
        }
        if (tid < 32) {
            int v = v0 + tid;
            bool ok = (v < n);
            const float* src = hb + (size_t)(ok ? v : 0) * 6;
            uint32_t dst = (uint32_t)__cvta_generic_to_shared(&xs[stage][tid]);
            asm volatile("cp.async.ca.shared.global [%0], [%1], 8, %2;\n"
                         :: "r"(dst), "l"(src), "r"(ok ? 8 : 0));
        }
    };

    load_tile(0, 0);
    cp_commit();

    for (int t = 0; t < ntiles; t++) {
        int cur = t & 1;
        if (t + 1 < ntiles) {
            load_tile(t + 1, (t + 1) & 1);
            cp_commit();
            cp_wait<1>();
        } else {
            cp_wait<0>();
        }
        __syncthreads();
#pragma unroll
        for (int v = 0; v < 32; v++) {
            float a = As[cur][v][tid];
            float2 x = xs[cur][v];
            a0 = fmaf(a, x.x, a0);
            a1 = fmaf(a, x.y, a1);
        }
        __syncthreads();
    }
    int w = w0 + tid;
    if (w < n) {
        float* op = buf + ((size_t)bt * n + w) * 6;
        op[sOut * 2]     = kAL * op[0] + a0;
        op[sOut * 2 + 1] = kAL * op[1] + a1;
    }
}

// pack step inputs: chainZ slice0 = [cur, hidden, 0pad]; chainC slice0 = [cur, 0..]
__global__ void k_pack(const float* __restrict__ cur, size_t curBs,
                       const float* __restrict__ chainS,
                       float* __restrict__ chainZ, float* __restrict__ chainC, int n)
{
    cudaTriggerProgrammaticLaunchCompletion();
    int i = blockIdx.x * blockDim.x + threadIdx.x;
    int total = cB * n * CP;
    if (i >= total) return;
    int c = i % CP;
    int row = i / CP;
    int nn = row % n, b = row / n;
    float vz = 0.f, vc = 0.f;
    if (c < cF) {
        float x = cur[(size_t)b * curBs + (size_t)nn * cF + c];
        vz = x; vc = x;
    } else if (c < cF + cH) {
        vz = chainS[(size_t)row * LDCH + (c - cF)];
    }
    chainZ[(size_t)row * LDCH + c] = vz;
    chainC[(size_t)row * LDCH + c] = vc;
}

// fused: gs, gt (K=192 over chainS), then ns, nt
__global__ void k_agg(const float* __restrict__ cur, size_t curBs,
                      const float* __restrict__ chainS,
                      const float* __restrict__ a1w, const float* __restrict__ a1b,
                      const float* __restrict__ a2w, const float* __restrict__ a2b,
                      const float* __restrict__ sw, const float* __restrict__ sb,
                      const float* __restrict__ tw, const float* __restrict__ tb,
                      float* __restrict__ ns, float* __restrict__ nt, int n)
{
    int gid = blockIdx.x * blockDim.x + threadIdx.x;
    int total = cB * n * cHYP;
    if (gid >= total) return;
    int j = gid & (cHYP - 1);
    int row = gid / cHYP;
    int nn = row % n, b = row / n;

    const float* ch = chainS + (size_t)row * LDCH;
    float g1 = a1b[j], g2 = a2b[j];
#pragma unroll
    for (int s = 0; s < 3; s++) {
        const float* cs = ch + s * CP;
        const float* w1 = a1w + (size_t)s * cH * cHYP + j;
        const float* w2 = a2w + (size_t)s * cH * cHYP + j;
#pragma unroll 8
        for (int c = 0; c < cH; c++) {
            float v = cs[c];
            g1 = fmaf(v, w1[c * cHYP], g1);
            g2 = fmaf(v, w2[c * cHYP], g2);
        }
    }
    const float* xr = cur + (size_t)b * curBs + (size_t)nn * cF;
    float x0 = xr[0], x1 = xr[1];
    float ps = sb[j] + x0 * sw[j] + x1 * sw[cHYP + j];
    float pt = tb[j] + x0 * tw[j] + x1 * tw[cHYP + j];
    ns[gid] = tanh_fast(kTAU * ps * g1);
    nt[gid] = tanh_fast(kTAU * pt * g2);
}

// adp rows (4 per block) -> combined coefficient (BE*adp + GA*adj) as tf32 hi/lo
__global__ __launch_bounds__(128) void k_adpcoef(
    const float* __restrict__ ns, const float* __restrict__ nt,
    const float* __restrict__ adj,
    uint32_t* __restrict__ coefHi, uint32_t* __restrict__ coefLo, int n)
{
    int b = blockIdx.y, i0 = blockIdx.x * 4;
    int tid = threadIdx.x;
    int lane = tid & 31, warp = tid >> 5;

    __shared__ float nsr[4][16], ntr[4][16];
    __shared__ float rowbuf[4][512];
    __shared__ float red[4][4];
    __shared__ float invs[4];

    if (tid < 64) {
        int ii = tid >> 4, c = tid & 15;
        nsr[ii][c] = ns[((size_t)b * n + i0 + ii) * 16 + c];
    } else {
        int t = tid - 64;
        int ii = t >> 4, c = t & 15;
        ntr[ii][c] = nt[((size_t)b * n + i0 + ii) * 16 + c];
    }
    __syncthreads();

    float lsum[4] = {0.f, 0.f, 0.f, 0.f};
    for (int m = tid; m < n; m += 128) {
        const float4* nsm = (const float4*)(ns + ((size_t)b * n + m) * 16);
        const float4* ntm = (const float4*)(nt + ((size_t)b * n + m) * 16);
        float4 s0 = nsm[0], s1 = nsm[1], s2 = nsm[2], s3 = nsm[3];
        float4 t0 = ntm[0], t1 = ntm[1], t2 = ntm[2], t3 = ntm[3];
        float sm[16] = {s0.x,s0.y,s0.z,s0.w, s1.x,s1.y,s1.z,s1.w,
                        s2.x,s2.y,s2.z,s2.w, s3.x,s3.y,s3.z,s3.w};
        float tm[16] = {t0.x,t0.y,t0.z,t0.w, t1.x,t1.y,t1.z,t1.w,
                        t2.x,t2.y,t2.z,t2.w, t3.x,t3.y,t3.z,t3.w};
#pragma unroll
        for (int ii = 0; ii < 4; ii++) {
            float a = 0.f;
#pragma unroll
            for (int c = 0; c < 16; c++)
                a += nsr[ii][c] * tm[c] - ntr[ii][c] * sm[c];
            float v = fmaxf(tanh_fast(kTAU * a), 0.f);
            if (m == i0 + ii) v += 1.f;
            rowbuf[ii][m] = v;
            lsum[ii] += v;
        }
    }
#pragma unroll
    for (int ii = 0; ii < 4; ii++) {
        float s = lsum[ii];
#pragma unroll
        for (int o = 16; o > 0; o >>= 1) s += __shfl_xor_sync(0xffffffffu, s, o);
        if (lane == 0) red[ii][warp] = s;
    }
    __syncthreads();
    if (tid < 4)
        invs[tid] = kBE / (red[tid][0] + red[tid][1] + red[tid][2] + red[tid][3]);
    __syncthreads();

    for (int m = tid; m < n; m += 128) {
#pragma unroll
        for (int ii = 0; ii < 4; ii++) {
            float v = rowbuf[ii][m] * invs[ii] + kGA * adj[(size_t)(i0 + ii) * n + m];
            size_t idx = ((size_t)b * n + i0 + ii) * n + m;
            uint32_t h = f2tf(v);
            coefHi[idx] = h;
            coefLo[idx] = f2tf(v - __uint_as_float(h));
        }
    }
}

// fused z & r gates; writes r*hidden into chainC slice0
__global__ void k_gate2(const float* __restrict__ chainZ, const float* __restrict__ chainS,
                        float* __restrict__ chainC,
                        const float* __restrict__ zw, const float* __restrict__ zbv,
                        const float* __restrict__ rw, const float* __restrict__ rbv,
                        float* __restrict__ zout, int n)
{
    cudaTriggerProgrammaticLaunchCompletion();
    int gid = blockIdx.x * blockDim.x + threadIdx.x;
    int total = cB * n * cH;
    if (gid >= total) return;
    int m = gid & (cH - 1);
    int row = gid >> 6;

    const float* ch = chainZ + (size_t)row * LDCH;
    float az = zbv[m], ar = rbv[m];
#pragma unroll
    for (int s = 0; s < 3; s++) {
        const float* cs = ch + s * CP;
        const float* wz = zw + (size_t)s * 66 * cH + m;
        const float* wr = rw + (size_t)s * 66 * cH + m;
#pragma unroll 6
        for (int c = 0; c < 66; c++) {
            float v = cs[c];
            az = fmaf(v, wz[c * cH], az);
            ar = fmaf(v, wr[c * cH], ar);
        }
    }
    float z = sigmoid_fast(az);
    float r = sigmoid_fast(ar);
    zout[gid] = z;
    chainC[(size_t)row * LDCH + cF + m] = r * chainS[(size_t)row * LDCH + m];
}

// fused c-gate + GRU hidden update; optionally packs next step inputs
__global__ void k_gcu(const float* __restrict__ chainC, float* __restrict__ chainS,
                      const float* __restrict__ zbuf,
                      const float* __restrict__ cw, const float* __restrict__ cbv,
                      const float* __restrict__ nextCur, size_t nextBs,
                      float* __restrict__ chainZ, float* __restrict__ chainCp, int n)
{
    cudaTriggerProgrammaticLaunchCompletion();
    int gid = blockIdx.x * blockDim.x + threadIdx.x;
    int total = cB * n * cH;
    if (gid >= total) return;
    int m = gid & (cH - 1);
    int row = gid >> 6;

    const float* ch = chainC + (size_t)row * LDCH;
    float ac = cbv[m];
#pragma unroll
    for (int s = 0; s < 3; s++) {
        const float* cs = ch + s * CP;
        const float* wc = cw + (size_t)s * 66 * cH + m;
#pragma unroll 6
        for (int c = 0; c < 66; c++)
            ac = fmaf(cs[c], wc[c * cH], ac);
    }
    float cval = tanh_fast(ac);
    float z = zbuf[gid];
    float* hp = chainS + (size_t)row * LDCH + m;
    float hnew = z * (*hp) + (1.f - z) * cval;
    *hp = hnew;
    if (nextCur) {
        chainZ[(size_t)row * LDCH + cF + m] = hnew;
        if (m < cF) {
            int nn = row % n, b = row / n;
            float x = nextCur[(size_t)b * nextBs + (size_t)nn * cF + m];
            chainZ[(size_t)row * LDCH + m]  = x;
            chainCp[(size_t)row * LDCH + m] = x;
        }
    }
}

// q/k projections for attention
__global__ void k_qk(const float* __restrict__ X,
                     const float* __restrict__ wqw, const float* __restrict__ wqb,
                     const float* __restrict__ wkw, const float* __restrict__ wkb,
                     float* __restrict__ q, float* __restrict__ kk, int n)
{
    int i = blockIdx.x * blockDim.x + threadIdx.x;
    int total = cB4 * n * cD;
    if (i >= total) return;
    int d = i % cD;
    int row = i / cD;
    int nn = row % n, bt = row / n;
    int b = bt >> 2, t = bt & 3;
    const float* xr = X + ((((size_t)b * cT) + (cT - 4) + t) * n + nn) * cF;
    kk[i] = wkb[d] + xr[0] * wkw[d] + xr[1] * wkw[cD + d];
    if (t == 3)
        q[((size_t)b * n + nn) * cD + d] = wqb[d] + xr[0] * wqw[d] + xr[1] * wqw[cD + d];
}

// scores + softmax + A_tgn = GA*(adj + attn); 4 rows i per block
__global__ __launch_bounds__(128) void k_attn(
    const float* __restrict__ q, const float* __restrict__ kk,
    const float* __restrict__ tw, const float* __restrict__ adj,
    float* __restrict__ Atgn, int n)
{
    int bt = blockIdx.y, i0 = blockIdx.x * 4;
    int b = bt >> 2;
    int tid = threadIdx.x;
    int lane = tid & 31, warp = tid >> 5;

    __shared__ float qd[4][8], twv[8];
    __shared__ float rowbuf[4][512];
    __shared__ float red[4][4];
    __shared__ float scal[4];

    if (tid < 32) {
        int ii = tid >> 3, d = tid & 7;
        qd[ii][d] = q[((size_t)b * n + i0 + ii) * 8 + d];
    } else if (tid < 40) {
        twv[tid - 32] = tw[tid - 32];
    }
    __syncthreads();

    float lmax[4] = {-1e30f, -1e30f, -1e30f, -1e30f};
    for (int j = tid; j < n; j += 128) {
        const float4* kj4 = (const float4*)(kk + ((size_t)bt * n + j) * 8);
        float4 k0 = kj4[0], k1 = kj4[1];
        float kj[8] = {k0.x,k0.y,k0.z,k0.w, k1.x,k1.y,k1.z,k1.w};
#pragma unroll
        for (int ii = 0; ii < 4; ii++) {
            float s = 0.f;
#pragma unroll
            for (int d = 0; d < 8; d++)
                s = fmaf(tanh_fast(qd[ii][d] + kj[d]), twv[d], s);
            rowbuf[ii][j] = s;
            lmax[ii] = fmaxf(lmax[ii], s);
        }
    }
#pragma unroll
    for (int ii = 0; ii < 4; ii++) {
        float s = lmax[ii];
#pragma unroll
        for (int o = 16; o > 0; o >>= 1) s = fmaxf(s, __shfl_xor_sync(0xffffffffu, s, o));
        if (lane == 0) red[ii][warp] = s;
    }
    __syncthreads();
    if (tid < 4)
        scal[tid] = fmaxf(fmaxf(red[tid][0], red[tid][1]), fmaxf(red[tid][2], red[tid][3]));
    __syncthreads();

    float lsum[4] = {0.f, 0.f, 0.f, 0.f};
    for (int j = tid; j < n; j += 128) {
#pragma unroll
        for (int ii = 0; ii < 4; ii++) {
            float e = __expf(rowbuf[ii][j] - scal[ii]);
            rowbuf[ii][j] = e;
            lsum[ii] += e;
        }
    }
#pragma unroll
    for (int ii = 0; ii < 4; ii++) {
        float s = lsum[ii];
#pragma unroll
        for (int o = 16; o > 0; o >>= 1) s += __shfl_xor_sync(0xffffffffu, s, o);
        if (lane == 0) red[ii][warp] = s;
    }
    __syncthreads();
    if (tid < 4)
        scal[tid] = 1.f / (red[tid][0] + red[tid][1] + red[tid][2] + red[tid][3]);
    __syncthreads();

    for (int j = tid; j < n; j += 128) {
#pragma unroll
        for (int ii = 0; ii < 4; ii++)
            Atgn[((size_t)bt * n + i0 + ii) * n + j] =
                kGA * (adj[(size_t)(i0 + ii) * n + j] + rowbuf[ii][j] * scal[ii]);
    }
}

__global__ void k_pack_tgn(const float* __restrict__ X, float* __restrict__ chainT, int n)
{
    int i = blockIdx.x * blockDim.x + threadIdx.x;
    int total = cB4 * n * cF;
    if (i >= total) return;
    int f = i % cF;
    int row = i / cF;
    int nn = row % n, bt = row / n;
    int b = bt >> 2, t = bt & 3;
    chainT[(size_t)row * 6 + f] =
        X[((((size_t)b * cT) + (cT - 4) + t) * n + nn) * cF + f];
}

// fused tgn matmul + relu + sum over t
__global__ void k_tgn_out(const float* __restrict__ chainT,
                          const float* __restrict__ tw, const float* __restrict__ tb,
                          float* __restrict__ tar2, int n)
{
    int gid = blockIdx.x * blockDim.x + threadIdx.x;
    int total = cB * n * cTGN;
    if (gid >= total) return;
    int m = gid & (cTGN - 1);
    int row = gid / cTGN;
    int nn = row % n, b = row / n;
    float tot = 0.f;
#pragma unroll
    for (int t = 0; t < 4; t++) {
        const float* cr = chainT + (((size_t)(b * 4 + t) * n) + nn) * 6;
        float s = tb[m];
#pragma unroll
        for (int k = 0; k < 6; k++)
            s = fmaf(cr[k], tw[k * cTGN + m], s);
        tot += fmaxf(s, 0.f);
    }
    tar2[gid] = tot;
}

// generic small FC: in1 (sliced) [+ in2 dense-ish]; mode 0 plain, 1 transposed store
__global__ void k_fc(const float* __restrict__ in1, int ld1, int sw1, int C1, int ns1,
                     const float* __restrict__ in2, int ld2, int C2,
                     const float* __restrict__ W, const float* __restrict__ Bv, int M,
                     float* __restrict__ out, int mode, int n, int rows)
{
    int gid = blockIdx.x * blockDim.x + threadIdx.x;
    if (gid >= rows * M) return;
    int m = gid % M;
    int row = gid / M;
    float acc = Bv[m];
    int k = 0;
    const float* r1 = in1 + (size_t)row * ld1;
    for (int s = 0; s < ns1; s++)
        for (int c = 0; c < C1; c++)
            acc = fmaf(r1[s * sw1 + c], W[(k++) * M + m], acc);
    if (in2) {
        const float* r2 = in2 + (size_t)row * ld2;
        for (int c = 0; c < C2; c++)
            acc = fmaf(r2[c], W[(k++) * M + m], acc);
    }
    if (mode == 0) out[(size_t)row * M + m] = acc;
    else {
        int nn = row % n, b = row / n;
        out[((size_t)b * M + m) * n + nn] = acc;
    }
}

// ---------------- host orchestration ----------------

struct Ptrs {
    float *chainS, *chainZ, *chainC, *ns, *nt, *z, *adjS;
    uint32_t *coefHi, *coefLo, *C1Hi, *C1Lo, *C2Hi, *C2Lo;
    float *Atgn, *q, *k, *chainT, *tar2, *gat;
};

// k_gconv2 launch, optionally with PDL (programmatic stream serialization)
static void launch_gconv(bool pdl, dim3 grid, dim3 block,
    float* buf, int C, int sIn, int sOut,
    const uint32_t* Ahi, const uint32_t* Alo, size_t Abs, int n)
{
    cudaLaunchConfig_t cfg = {};
    cfg.gridDim = grid; cfg.blockDim = block;
    cfg.dynamicSmemBytes = 0; cfg.stream = 0;
    cudaLaunchAttribute attr[1];
    attr[0].id = cudaLaunchAttributeProgrammaticStreamSerialization;
    attr[0].val.programmaticStreamSerializationAllowed = 1;
    cfg.attrs = attr;
    cfg.numAttrs = pdl ? 1 : 0;
    cudaLaunchKernelEx(&cfg, k_gconv2, buf, C, sIn, sOut, Ahi, Alo, Abs, n);
}

static void launch_dual(dim3 grid, dim3 block,
    float* buf, int C,
    const uint32_t* a1h, const uint32_t* a1l,
    const uint32_t* a2h, const uint32_t* a2l, int n)
{
    cudaLaunchConfig_t cfg = {};
    cfg.gridDim = grid; cfg.blockDim = block;
    cfg.dynamicSmemBytes = GD_SMEM; cfg.stream = 0;
    cudaLaunchAttribute attr[1];
    attr[0].id = cudaLaunchAttributeProgrammaticStreamSerialization;
    attr[0].val.programmaticStreamSerializationAllowed = 1;
    cfg.attrs = attr;
    cfg.numAttrs = 1;
    cudaLaunchKernelEx(&cfg, k_gconv2dual, buf, C, a1h, a1l, a2h, a2l, n);
}

// One GRU step. Assumes chainZ/chainC slice0 are already packed for this step.
static void gru_step(const float* cur, size_t curBs, const float* adj,
                     const float* a1w, const float* a1b, const float* a2w, const float* a2b,
                     const float* sw, const float* sb, const float* tw, const float* tb,
                     const float* zw, const float* zb, const float* rw, const float* rb,
                     const float* cw, const float* cb,
                     const float* nextCur, size_t nextBs, const Ptrs& P)
{
    const int n = cN;
    dim3 gg(DIV_UP(n, 32), cB);
    dim3 bb(192);

    // S-chain dual gconv: PDL over gcu/pack (C1/C2 prefetch is safe pre-dep)
    launch_dual(gg, bb, P.chainS, cH, P.C1Hi, P.C1Lo, P.C2Hi, P.C2Lo, n);

    k_agg<<<DIV_UP(cB * n * cHYP, 256), 256>>>(cur, curBs, P.chainS,
        a1w, a1b, a2w, a2b, sw, sb, tw, tb, P.ns, P.nt, n);

    k_adpcoef<<<dim3(n / 4, cB), 128>>>(P.ns, P.nt, adj, P.coefHi, P.coefLo, n);

    // Zs1: NOT PDL'd (its coef is written by the immediate predecessor adpcoef)
    launch_gconv(false, gg, bb, P.chainZ, cF + cH, 0, 1, P.coefHi, P.coefLo, (size_t)n * n, n);
    // Zs2: PDL over Zs1 (coef safe, h guarded by grid-dep sync)
    launch_gconv(true,  gg, bb, P.chainZ, cF + cH, 1, 2, P.coefHi, P.coefLo, (size_t)n * n, n);

    k_gate2<<<DIV_UP(cB * n * cH, 256), 256>>>(P.chainZ, P.chainS, P.chainC,
        zw, zb, rw, rb, P.z, n);

    // Cs1: PDL over gate2 ; Cs2: PDL over Cs1
    launch_gconv(true, gg, bb, P.chainC, cF + cH, 0, 1, P.coefHi, P.coefLo, (size_t)n * n, n);
    launch_gconv(true, gg, bb, P.chainC, cF + cH, 1, 2, P.coefHi, P.coefLo, (size_t)n * n, n);

    k_gcu<<<DIV_UP(cB * n * cH, 256), 256>>>(P.chainC, P.chainS, P.z, cw, cb,
        nextCur, nextBs, P.chainZ, P.chainC, n);
}

extern "C" void kernel_launch(void* const* d_in, const int* in_sizes, int n_in,
                              void* d_out, int out_size)
{
    const float* X      = (const float*)d_in[0];
    const float* adj    = (const float*)d_in[1];
    const float* wq_w   = (const float*)d_in[7];
    const float* wq_b   = (const float*)d_in[8];
    const float* wk_w   = (const float*)d_in[9];
    const float* wk_b   = (const float*)d_in[10];
    const float* trans_w= (const float*)d_in[11];
    const float* tgn_w  = (const float*)d_in[12];
    const float* tgn_b  = (const float*)d_in[13];
    const float* agg1_w = (const float*)d_in[14];
    const float* agg1_b = (const float*)d_in[15];
    const float* agg2_w = (const float*)d_in[16];
    const float* agg2_b = (const float*)d_in[17];
    const float* src_w  = (const float*)d_in[18];
    const float* src_b  = (const float*)d_in[19];
    const float* tgt_w  = (const float*)d_in[20];
    const float* tgt_b  = (const float*)d_in[21];
    const float* gz_w   = (const float*)d_in[22];
    const float* gz_b   = (const float*)d_in[23];
    const float* gr_w   = (const float*)d_in[24];
    const float* gr_b   = (const float*)d_in[25];
    const float* gc_w   = (const float*)d_in[26];
    const float* gc_b   = (const float*)d_in[27];
    const float* fcs_w  = (const float*)d_in[28];
    const float* fcs_b  = (const float*)d_in[29];
    const float* fcm_w  = (const float*)d_in[30];
    const float* fcm_b  = (const float*)d_in[31];
    float* out = (float*)d_out;

    cudaFuncSetAttribute(k_gconv2dual, cudaFuncAttributeMaxDynamicSharedMemorySize, GD_SMEM);

    Ptrs P;
    cudaGetSymbolAddress((void**)&P.chainS, g_chainS);
    cudaGetSymbolAddress((void**)&P.chainZ, g_chainZ);
    cudaGetSymbolAddress((void**)&P.chainC, g_chainC);
    cudaGetSymbolAddress((void**)&P.coefHi, g_coefHi);
    cudaGetSymbolAddress((void**)&P.coefLo, g_coefLo);
    cudaGetSymbolAddress((void**)&P.adjS,   g_adjS);
    cudaGetSymbolAddress((void**)&P.C1Hi,   g_C1Hi);
    cudaGetSymbolAddress((void**)&P.C1Lo,   g_C1Lo);
    cudaGetSymbolAddress((void**)&P.C2Hi,   g_C2Hi);
    cudaGetSymbolAddress((void**)&P.C2Lo,   g_C2Lo);
    cudaGetSymbolAddress((void**)&P.ns,     g_ns);
    cudaGetSymbolAddress((void**)&P.nt,     g_nt);
    cudaGetSymbolAddress((void**)&P.z,      g_z);
    cudaGetSymbolAddress((void**)&P.Atgn,   g_Atgn);
    cudaGetSymbolAddress((void**)&P.q,      g_q);
    cudaGetSymbolAddress((void**)&P.k,      g_k);
    cudaGetSymbolAddress((void**)&P.chainT, g_chainT);
    cudaGetSymbolAddress((void**)&P.tar2,   g_tar2);
    cudaGetSymbolAddress((void**)&P.gat,    g_gat);

    const size_t Xbs = (size_t)cT * cN * cF;

    // ---- fork: attention branch on side stream (depends only on X, adj) ----
    cudaEventRecord(g_ss.fork, 0);
    cudaStreamWaitEvent(g_ss.s, g_ss.fork, 0);

    k_qk<<<DIV_UP(cB4 * cN * cD, 256), 256, 0, g_ss.s>>>(X, wq_w, wq_b, wk_w, wk_b, P.q, P.k, cN);
    k_attn<<<dim3(cN / 4, cB4), 128, 0, g_ss.s>>>(P.q, P.k, trans_w, adj, P.Atgn, cN);
    k_pack_tgn<<<DIV_UP(cB4 * cN * cF, 256), 256, 0, g_ss.s>>>(X, P.chainT, cN);
    dim3 ggt(DIV_UP(cN, 128), cB4);
    k_gconv_f2<<<ggt, 128, 0, g_ss.s>>>(P.chainT, 0, 1, P.Atgn, cN);
    k_gconv_f2<<<ggt, 128, 0, g_ss.s>>>(P.chainT, 1, 2, P.Atgn, cN);
    k_tgn_out<<<DIV_UP(cB * cN * cTGN, 256), 256, 0, g_ss.s>>>(P.chainT, tgn_w, tgn_b, P.tar2, cN);
    k_fc<<<DIV_UP(cB * cN * cF, 256), 256, 0, g_ss.s>>>(P.tar2, cTGN, 0, cTGN, 1,
        nullptr, 0, 0, fcs_w, fcs_b, cF, P.gat, 0, cN, cB * cN);

    cudaEventRecord(g_ss.join, g_ss.s);

    // ---- main branch: precompute S-chain matrices + GRU warmup ----
    k_adj2<<<dim3(DIV_UP(cN, 32), DIV_UP(cN, 32)), dim3(32, 32)>>>(adj, P.adjS, cN);
    k_coefhl2<<<DIV_UP(cN * cN, 256), 256>>>(adj, P.adjS,
        P.C1Hi, P.C1Lo, P.C2Hi, P.C2Lo, cN);

    // hidden (chainS) = 0 — deterministic per call
    k_zero<<<DIV_UP(cB * cN * LDCH, 256), 256>>>(P.chainS, cB * cN * LDCH);

    // pack for step 0 (hidden = 0)
    k_pack<<<DIV_UP(cB * cN * CP, 256), 256>>>(X, Xbs, P.chainS, P.chainZ, P.chainC, cN);

    // warmup GRU steps: t = 0,4,8,12,16
    for (int t = 0; t + 4 < cT; t += 4) {
        const float* nextCur = (t + 8 < cT) ? (X + (size_t)(t + 4) * cN * cF) : nullptr;
        gru_step(X + (size_t)t * cN * cF, Xbs, adj,
                 agg1_w, agg1_b, agg2_w, agg2_b, src_w, src_b, tgt_w, tgt_b,
                 gz_w, gz_b, gr_w, gr_b, gc_w, gc_b,
                 nextCur, Xbs, P);
    }

    // ---- join: gat/tar2 ready before the final step ----
    cudaStreamWaitEvent(0, g_ss.join, 0);

    // pack + final GRU step
    k_pack<<<DIV_UP(cB * cN * CP, 256), 256>>>(P.gat, (size_t)cN * cF, P.chainS,
        P.chainZ, P.chainC, cN);
    gru_step(P.gat, (size_t)cN * cF, adj,
             agg1_w, agg1_b, agg2_w, agg2_b, src_w, src_b, tgt_w, tgt_b,
             gz_w, gz_b, gr_w, gr_b, gc_w, gc_b,
             nullptr, 0, P);

    // out[b, l, n] = concat([tar2, hidden]) @ fcm_w + fcm_b (transposed store)
    k_fc<<<DIV_UP(cB * cN * cLEN, 256), 256>>>(P.tar2, cTGN, 0, cTGN, 1,
        P.chainS, LDCH, cH, fcm_w, fcm_b, cLEN, out, 1, cN, cB * cN);
}

// round 17
// speedup vs baseline: 1.2387x; 1.2387x over previous
#include <cuda_runtime.h>
#include <cstdint>
#include <math.h>

#define DIV_UP(a,b) (((a)+(b)-1)/(b))

// Problem constants
constexpr int cB   = 16;
constexpr int cT   = 24;
constexpr int cN   = 500;
constexpr int cF   = 2;
constexpr int cH   = 64;
constexpr int cD   = 8;
constexpr int cTGN = 32;
constexpr int cHYP = 16;
constexpr int cLEN = 24;
constexpr int cB4  = cB * 4;

constexpr float kAL = 0.05f, kBE = 0.95f, kGA = 0.95f, kTAU = 2.0f;

// padded chain layout: 3 slices of 72 floats each, row stride 216
constexpr int CP   = 72;
constexpr int LDCH = 216;

// dual-gconv dynamic smem: 4 coef arrays x 2 stages + h x 2 stages
constexpr int GD_CF = 32 * 36 * 4;    // 4608 per coef tile
constexpr int GD_HS = 32 * 76 * 4;    // 9728 per h tile
constexpr int GD_SMEM = 8 * GD_CF + 2 * GD_HS;  // 56320

// ---------------- scratch ----------------
__device__ float g_chainS[cB * cN * LDCH];   // slice0 = hidden (persistent per call)
__device__ float g_chainZ[cB * cN * LDCH];
__device__ float g_chainC[cB * cN * LDCH];
__device__ uint32_t g_coefHi[(size_t)cB * cN * cN];
__device__ uint32_t g_coefLo[(size_t)cB * cN * cN];
__device__ float g_adjS[cN * cN];            // adj @ adj
__device__ uint32_t g_C1Hi[cN * cN];
__device__ uint32_t g_C1Lo[cN * cN];
__device__ uint32_t g_C2Hi[cN * cN];
__device__ uint32_t g_C2Lo[cN * cN];
__device__ float g_ns[cB * cN * cHYP];
__device__ float g_nt[cB * cN * cHYP];
__device__ float g_z[cB * cN * cH];
__device__ float g_Atgn[(size_t)cB4 * cN * cN];
__device__ float g_q[cB * cN * cD];
__device__ float g_k[cB4 * cN * cD];
__device__ float g_chainT[cB4 * cN * 6];
__device__ float g_tar2[cB * cN * cTGN];
__device__ float g_gat[cB * cN * cF];

// side stream + fork/join events, created ONCE at program load.
struct SideStream {
    cudaStream_t s = nullptr;
    cudaEvent_t fork = nullptr, join = nullptr;
    SideStream() {
        cudaStreamCreateWithFlags(&s, cudaStreamNonBlocking);
        cudaEventCreateWithFlags(&fork, cudaEventDisableTiming);
        cudaEventCreateWithFlags(&join, cudaEventDisableTiming);
    }
};
static SideStream g_ss;

__device__ __forceinline__ float tanh_fast(float x) {
    float y;
    asm("tanh.approx.f32 %0, %1;" : "=f"(y) : "f"(x));
    return y;
}
__device__ __forceinline__ float sigmoid_fast(float x) {
    return 1.f / (1.f + __expf(-x));
}
__device__ __forceinline__ void cp_async16(uint32_t saddr, const void* gptr, int psize) {
    asm volatile("cp.async.ca.shared.global [%0], [%1], 16, %2;\n"
                 :: "r"(saddr), "l"(gptr), "r"(psize));
}
__device__ __forceinline__ void cp_commit() {
    asm volatile("cp.async.commit_group;\n");
}
template <int N>
__device__ __forceinline__ void cp_wait() {
    asm volatile("cp.async.wait_group %0;\n" :: "n"(N));
}
__device__ __forceinline__ uint32_t f2tf(float x) {
    uint32_t r;
    asm("cvt.rna.tf32.f32 %0, %1;" : "=r"(r) : "f"(x));
    return r;
}
__device__ __forceinline__ void mma_tf32(float* c,
    uint32_t a0, uint32_t a1, uint32_t a2, uint32_t a3,
    uint32_t b0, uint32_t b1)
{
    asm volatile(
        "mma.sync.aligned.m16n8k8.row.col.f32.tf32.tf32.f32 "
        "{%0,%1,%2,%3}, {%4,%5,%6,%7}, {%8,%9}, {%0,%1,%2,%3};"
        : "+f"(c[0]), "+f"(c[1]), "+f"(c[2]), "+f"(c[3])
        : "r"(a0), "r"(a1), "r"(a2), "r"(a3), "r"(b0), "r"(b1));
}

// ---------------- kernels ----------------

__global__ void k_zero(float* p, int ntot) {
    int i = blockIdx.x * blockDim.x + threadIdx.x;
    if (i < ntot) p[i] = 0.f;
}

// S = adj @ adj (row-major), 32x32 tiled fp32
__global__ __launch_bounds__(1024) void k_adj2(
    const float* __restrict__ adj, float* __restrict__ S, int n)
{
    int tx = threadIdx.x, ty = threadIdx.y;
    int w = blockIdx.x * 32 + tx;
    int u = blockIdx.y * 32 + ty;
    __shared__ float As[32][33];
    __shared__ float Bs[32][33];
    float acc = 0.f;
    for (int v0 = 0; v0 < n; v0 += 32) {
        int va = v0 + tx, vb = v0 + ty;
        As[ty][tx] = (u < n && va < n) ? adj[(size_t)u * n + va] : 0.f;
        Bs[ty][tx] = (vb < n && w < n) ? adj[(size_t)vb * n + w] : 0.f;
        __syncthreads();
#pragma unroll
        for (int k = 0; k < 32; k++)
            acc = fmaf(As[ty][k], Bs[k][tx], acc);
        __syncthreads();
    }
    if (u < n && w < n) S[(size_t)u * n + w] = acc;
}

// C1 = GA*adj + AL*I ; C2 = AL*I + GA*AL*adj + GA^2*(adj@adj) ; emit tf32 hi/lo
__global__ void k_coefhl2(const float* __restrict__ adj, const float* __restrict__ S,
                          uint32_t* __restrict__ c1h, uint32_t* __restrict__ c1l,
                          uint32_t* __restrict__ c2h, uint32_t* __restrict__ c2l, int n)
{
    int i = blockIdx.x * blockDim.x + threadIdx.x;
    if (i >= n * n) return;
    bool diag = (i / n) == (i % n);
    float a = adj[i];
    float v1 = kGA * a + (diag ? kAL : 0.f);
    float v2 = (diag ? kAL : 0.f) + kGA * kAL * a + kGA * kGA * S[i];
    uint32_t h1 = f2tf(v1);
    c1h[i] = h1; c1l[i] = f2tf(v1 - __uint_as_float(h1));
    uint32_t h2 = f2tf(v2);
    c2h[i] = h2; c2l[i] = f2tf(v2 - __uint_as_float(h2));
}

// Dual-output tensor-core graph conv for the S-chain (3xTF32, AL folded into coefs):
//   slice1[w,c] = sum_v C1[v,w]*h[v,c] ; slice2[w,c] = sum_v C2[v,w]*h[v,c]
// Shares the h tile (loaded+converted once) between both A operands.
__global__ __launch_bounds__(192) void k_gconv2dual(
    float* __restrict__ buf, int C,
    const uint32_t* __restrict__ A1hi, const uint32_t* __restrict__ A1lo,
    const uint32_t* __restrict__ A2hi, const uint32_t* __restrict__ A2lo, int n)
{
    extern __shared__ char sm[];
    const uint32_t smbase = (uint32_t)__cvta_generic_to_shared(sm);

    const int b  = blockIdx.y;
    const int w0 = blockIdx.x * 32;
    const int tid = threadIdx.x;
    const int lane = tid & 31;
    const int warp = tid >> 5;
    const int wb = (warp & 1) * 16;
    const int cb = (warp >> 1) * 24;
    const int lq = lane >> 2;
    const int lr = lane & 3;

    float acc1[3][4], acc2[3][4];
#pragma unroll
    for (int i = 0; i < 3; i++)
#pragma unroll
        for (int j = 0; j < 4; j++) { acc1[i][j] = 0.f; acc2[i][j] = 0.f; }

    const float* hb = buf + (size_t)b * n * LDCH;   // slice0
    const uint32_t* srcs[4] = {A1hi, A1lo, A2hi, A2lo};

    const int ntiles = DIV_UP(n, 32);

    auto load_tile = [&](int t, int stage) {
        int v0 = t * 32;
        // 4 coef tiles: 4 x 256 16B-chunks = 1024
#pragma unroll
        for (int it = 0; it < 6; it++) {
            int idx = tid + it * 192;
            if (idx < 1024) {
                int arr = idx >> 8, rem = idx & 255;
                int vi = rem >> 3, seg = rem & 7;
                int v = v0 + vi, w = w0 + seg * 4;
                bool ok = (v < n) && (w < n);
                size_t off = (size_t)(ok ? v : 0) * n + (ok ? w : 0);
                uint32_t dst = smbase + arr * 2 * GD_CF + stage * GD_CF
                             + (vi * 36 + seg * 4) * 4;
                cp_async16(dst, srcs[arr] + off, ok ? 16 : 0);
            }
        }
        // h tile: 576 16B-chunks, exactly 3/thread
#pragma unroll
        for (int it = 0; it < 3; it++) {
            int idx = tid + it * 192;
            int vi = idx / 18, seg = idx % 18;
            int v = v0 + vi;
            bool ok = (v < n);
            uint32_t dst = smbase + 8 * GD_CF + stage * GD_HS + (vi * 76 + seg * 4) * 4;
            cp_async16(dst, hb + (size_t)(ok ? v : 0) * LDCH + seg * 4, ok ? 16 : 0);
        }
    };

    load_tile(0, 0);
    cp_commit();

    for (int t = 0; t < ntiles; t++) {
        int cur = t & 1;
        if (t + 1 < ntiles) {
            load_tile(t + 1, (t + 1) & 1);
            cp_commit();
            cp_wait<1>();
        } else {
            cp_wait<0>();
        }
        __syncthreads();

        const uint32_t (*h1)[36] = (const uint32_t(*)[36])(sm + 0 * GD_CF + cur * GD_CF);
        const uint32_t (*l1)[36] = (const uint32_t(*)[36])(sm + 2 * GD_CF + cur * GD_CF);
        const uint32_t (*h2)[36] = (const uint32_t(*)[36])(sm + 4 * GD_CF + cur * GD_CF);
        const uint32_t (*l2)[36] = (const uint32_t(*)[36])(sm + 6 * GD_CF + cur * GD_CF);
        const float (*hsc)[76]   = (const float(*)[76])(sm + 8 * GD_CF + cur * GD_HS);

#pragma unroll
        for (int k8 = 0; k8 < 4; k8++) {
            int kb = k8 * 8;
            uint32_t a1h0 = h1[kb + lr][wb + lq];
            uint32_t a1h1 = h1[kb + lr][wb + lq + 8];
            uint32_t a1h2 = h1[kb + lr + 4][wb + lq];
            uint32_t a1h3 = h1[kb + lr + 4][wb + lq + 8];
            uint32_t a1l0 = l1[kb + lr][wb + lq];
            uint32_t a1l1 = l1[kb + lr][wb + lq + 8];
            uint32_t a1l2 = l1[kb + lr + 4][wb + lq];
            uint32_t a1l3 = l1[kb + lr + 4][wb + lq + 8];
            uint32_t a2h0 = h2[kb + lr][wb + lq];
            uint32_t a2h1 = h2[kb + lr][wb + lq + 8];
            uint32_t a2h2 = h2[kb + lr + 4][wb + lq];
            uint32_t a2h3 = h2[kb + lr + 4][wb + lq + 8];
            uint32_t a2l0 = l2[kb + lr][wb + lq];
            uint32_t a2l1 = l2[kb + lr][wb + lq + 8];
            uint32_t a2l2 = l2[kb + lr + 4][wb + lq];
            uint32_t a2l3 = l2[kb + lr + 4][wb + lq + 8];

#pragma unroll
            for (int ct = 0; ct < 3; ct++) {
                float br0 = hsc[kb + lr][cb + ct * 8 + lq];
                float br1 = hsc[kb + lr + 4][cb + ct * 8 + lq];
                uint32_t bh0 = f2tf(br0), bh1 = f2tf(br1);
                uint32_t bl0 = f2tf(br0 - __uint_as_float(bh0));
                uint32_t bl1 = f2tf(br1 - __uint_as_float(bh1));

                mma_tf32(acc1[ct], a1h0, a1h1, a1h2, a1h3, bh0, bh1);
                mma_tf32(acc1[ct], a1l0, a1l1, a1l2, a1l3, bh0, bh1);
                mma_tf32(acc1[ct], a1h0, a1h1, a1h2, a1h3, bl0, bl1);
                mma_tf32(acc2[ct], a2h0, a2h1, a2h2, a2h3, bh0, bh1);
                mma_tf32(acc2[ct], a2l0, a2l1, a2l2, a2l3, bh0, bh1);
                mma_tf32(acc2[ct], a2h0, a2h1, a2h2, a2h3, bl0, bl1);
            }
        }
        __syncthreads();
    }

    int wr0 = w0 + wb + lq;
    int wr1 = wr0 + 8;
#pragma unroll
    for (int ct = 0; ct < 3; ct++) {
        int c = cb + ct * 8 + lr * 2;
        if (wr0 < n) {
            float* op = buf + ((size_t)b * n + wr0) * LDCH;
            if (c < C)     { op[CP + c]     = acc1[ct][0]; op[2 * CP + c]     = acc2[ct][0]; }
            if (c + 1 < C) { op[CP + c + 1] = acc1[ct][1]; op[2 * CP + c + 1] = acc2[ct][1]; }
        }
        if (wr1 < n) {
            float* op = buf + ((size_t)b * n + wr1) * LDCH;
            if (c < C)     { op[CP + c]     = acc1[ct][2]; op[2 * CP + c]     = acc2[ct][2]; }
            if (c + 1 < C) { op[CP + c + 1] = acc1[ct][3]; op[2 * CP + c + 1] = acc2[ct][3]; }
        }
    }
}

// Tensor-core graph conv (3xTF32, A pre-split hi/lo), double-buffered cp.async.
// out[w, sOut*CP+c] = AL*buf[w,c] + sum_v Asplit[b,v,w] * buf[v, sIn*CP+c]
__global__ __launch_bounds__(192) void k_gconv2(
    float* __restrict__ buf, int C, int sIn, int sOut,
    const uint32_t* __restrict__ Ahi, const uint32_t* __restrict__ Alo,
    size_t Abs, int n)
{
    const int b  = blockIdx.y;
    const int w0 = blockIdx.x * 32;
    const int tid = threadIdx.x;
    const int lane = tid & 31;
    const int warp = tid >> 5;
    const int wb = (warp & 1) * 16;
    const int cb = (warp >> 1) * 24;
    const int lq = lane >> 2;
    const int lr = lane & 3;

    __shared__ uint32_t cfh[2][32][36];
    __shared__ uint32_t cfl[2][32][36];
    __shared__ float hs[2][32][76];

    float acc[3][4];
#pragma unroll
    for (int i = 0; i < 3; i++)
#pragma unroll
        for (int j = 0; j < 4; j++) acc[i][j] = 0.f;

    const uint32_t* AhiB = Ahi + (size_t)b * Abs;
    const uint32_t* AloB = Alo + (size_t)b * Abs;
    const float* hb = buf + (size_t)b * n * LDCH + sIn * CP;

    const int ntiles = DIV_UP(n, 32);

    auto load_tile = [&](int t, int stage) {
        int v0 = t * 32;
#pragma unroll
        for (int it = 0; it < 2; it++) {
            int idx = tid + it * 192;
            if (idx < 256) {
                int vi = idx >> 3, seg = idx & 7;
                int v = v0 + vi, w = w0 + seg * 4;
                bool ok = (v < n) && (w < n);
                size_t off = (size_t)(ok ? v : 0) * n + (ok ? w : 0);
                uint32_t dh = (uint32_t)__cvta_generic_to_shared(&cfh[stage][vi][seg * 4]);
                uint32_t dl = (uint32_t)__cvta_generic_to_shared(&cfl[stage][vi][seg * 4]);
                cp_async16(dh, AhiB + off, ok ? 16 : 0);
                cp_async16(dl, AloB + off, ok ? 16 : 0);
            }
        }
#pragma unroll
        for (int it = 0; it < 3; it++) {
            int idx = tid + it * 192;
            int vi = idx / 18, seg = idx % 18;
            int v = v0 + vi;
            bool ok = (v < n);
            const float* src = hb + (size_t)(ok ? v : 0) * LDCH + seg * 4;
            uint32_t dst = (uint32_t)__cvta_generic_to_shared(&hs[stage][vi][seg * 4]);
            cp_async16(dst, src, ok ? 16 : 0);
        }
    };

    load_tile(0, 0);
    cp_commit();

    for (int t = 0; t < ntiles; t++) {
        int cur = t & 1;
        if (t + 1 < ntiles) {
            load_tile(t + 1, (t + 1) & 1);
            cp_commit();
            cp_wait<1>();
        } else {
            cp_wait<0>();
        }
        __syncthreads();

        const uint32_t (*ch)[36] = cfh[cur];
        const uint32_t (*cl)[36] = cfl[cur];
        const float (*hsc)[76] = hs[cur];

#pragma unroll
        for (int k8 = 0; k8 < 4; k8++) {
            int kb = k8 * 8;
            uint32_t ah0 = ch[kb + lr][wb + lq];
            uint32_t ah1 = ch[kb + lr][wb + lq + 8];
            uint32_t ah2 = ch[kb + lr + 4][wb + lq];
            uint32_t ah3 = ch[kb + lr + 4][wb + lq + 8];
            uint32_t al0 = cl[kb + lr][wb + lq];
            uint32_t al1 = cl[kb + lr][wb + lq + 8];
            uint32_t al2 = cl[kb + lr + 4][wb + lq];
            uint32_t al3 = cl[kb + lr + 4][wb + lq + 8];

#pragma unroll
            for (int ct = 0; ct < 3; ct++) {
                float br0 = hsc[kb + lr][cb + ct * 8 + lq];
                float br1 = hsc[kb + lr + 4][cb + ct * 8 + lq];
                uint32_t bh0 = f2tf(br0), bh1 = f2tf(br1);
                uint32_t bl0 = f2tf(br0 - __uint_as_float(bh0));
                uint32_t bl1 = f2tf(br1 - __uint_as_float(bh1));

                mma_tf32(acc[ct], ah0, ah1, ah2, ah3, bh0, bh1);
                mma_tf32(acc[ct], al0, al1, al2, al3, bh0, bh1);
                mma_tf32(acc[ct], ah0, ah1, ah2, ah3, bl0, bl1);
            }
        }
        __syncthreads();
    }

    int wr0 = w0 + wb + lq;
    int wr1 = wr0 + 8;
#pragma unroll
    for (int ct = 0; ct < 3; ct++) {
        int c = cb + ct * 8 + lr * 2;
        if (wr0 < n) {
            float* op = buf + ((size_t)b * n + wr0) * LDCH;
            if (c < C)     op[sOut * CP + c]     = kAL * op[c]     + acc[ct][0];
            if (c + 1 < C) op[sOut * CP + c + 1] = kAL * op[c + 1] + acc[ct][1];
        }
        if (wr1 < n) {
            float* op = buf + ((size_t)b * n + wr1) * LDCH;
            if (c < C)     op[sOut * CP + c]     = kAL * op[c]     + acc[ct][2];
            if (c + 1 < C) op[sOut * CP + c + 1] = kAL * op[c + 1] + acc[ct][3];
        }
    }
}

// C=2 graph conv for the TGN path (A already includes GA scaling)
__global__ __launch_bounds__(128) void k_gconv_f2(
    float* __restrict__ buf, int sIn, int sOut,
    const float* __restrict__ A, int n)
{
    int bt = blockIdx.y;
    int w0 = blockIdx.x * 128;
    int tid = threadIdx.x;
    __shared__ float As[2][32][132];
    __shared__ float2 xs[2][32];
    float a0 = 0.f, a1 = 0.f;
    const float* Ab = A + (size_t)bt * n * n;
    const float* hb = buf + (size_t)bt * n * 6 + sIn * 2;

    const int ntiles = DIV_UP(n, 32);

    auto load_tile = [&](int t, int stage) {
        int v0 = t * 32;
#pragma unroll
        for (int it = 0; it < 8; it++) {
            int idx = tid + it * 128;
            int vi = idx >> 5, seg = idx & 31;
            int v = v0 + vi, w = w0 + seg * 4;
            bool ok = (v < n) && (w < n);
            const float* src = Ab + (size_t)(ok ? v : 0) * n + (ok ? w : 0);
            uint32_t dst = (uint32_t)__cvta_generic_to_shared(&As[stage][vi][seg * 4]);
            cp_async16(dst, src, ok ? 16 : 0);
        }
        if (tid < 32) {
            int v = v0 + tid;
            bool ok = (v < n);
            const float* src = hb + (size_t)(ok ? v : 0) * 6;
            uint32_t dst = (uint32_t)__cvta_generic_to_shared(&xs[stage][tid]);
            asm volatile("cp.async.ca.shared.global [%0], [%1], 8, %2;\n"
                         :: "r"(dst), "l"(src), "r"(ok ? 8 : 0));
        }
    };

    load_tile(0, 0);
    cp_commit();

    for (int t = 0; t < ntiles; t++) {
        int cur = t & 1;
        if (t + 1 < ntiles) {
            load_tile(t + 1, (t + 1) & 1);
            cp_commit();
            cp_wait<1>();
        } else {
            cp_wait<0>();
        }
        __syncthreads();
#pragma unroll
        for (int v = 0; v < 32; v++) {
            float a = As[cur][v][tid];
            float2 x = xs[cur][v];
            a0 = fmaf(a, x.x, a0);
            a1 = fmaf(a, x.y, a1);
        }
        __syncthreads();
    }
    int w = w0 + tid;
    if (w < n) {
        float* op = buf + ((size_t)bt * n + w) * 6;
        op[sOut * 2]     = kAL * op[0] + a0;
        op[sOut * 2 + 1] = kAL * op[1] + a1;
    }
}

// pack step inputs: chainZ slice0 = [cur, hidden, 0pad]; chainC slice0 = [cur, 0..]
__global__ void k_pack(const float* __restrict__ cur, size_t curBs,
                       const float* __restrict__ chainS,
                       float* __restrict__ chainZ, float* __restrict__ chainC, int n)
{
    int i = blockIdx.x * blockDim.x + threadIdx.x;
    int total = cB * n * CP;
    if (i >= total) return;
    int c = i % CP;
    int row = i / CP;
    int nn = row % n, b = row / n;
    float vz = 0.f, vc = 0.f;
    if (c < cF) {
        float x = cur[(size_t)b * curBs + (size_t)nn * cF + c];
        vz = x; vc = x;
    } else if (c < cF + cH) {
        vz = chainS[(size_t)row * LDCH + (c - cF)];
    }
    chainZ[(size_t)row * LDCH + c] = vz;
    chainC[(size_t)row * LDCH + c] = vc;
}

// fused: gs, gt (K=192 over chainS), then ns, nt
__global__ void k_agg(const float* __restrict__ cur, size_t curBs,
                      const float* __restrict__ chainS,
                      const float* __restrict__ a1w, const float* __restrict__ a1b,
                      const float* __restrict__ a2w, const float* __restrict__ a2b,
                      const float* __restrict__ sw, const float* __restrict__ sb,
                      const float* __restrict__ tw, const float* __restrict__ tb,
                      float* __restrict__ ns, float* __restrict__ nt, int n)
{
    int gid = blockIdx.x * blockDim.x + threadIdx.x;
    int total = cB * n * cHYP;
    if (gid >= total) return;
    int j = gid & (cHYP - 1);
    int row = gid / cHYP;
    int nn = row % n, b = row / n;

    const float* ch = chainS + (size_t)row * LDCH;
    float g1 = a1b[j], g2 = a2b[j];
#pragma unroll
    for (int s = 0; s < 3; s++) {
        const float* cs = ch + s * CP;
        const float* w1 = a1w + (size_t)s * cH * cHYP + j;
        const float* w2 = a2w + (size_t)s * cH * cHYP + j;
#pragma unroll 8
        for (int c = 0; c < cH; c++) {
            float v = cs[c];
            g1 = fmaf(v, w1[c * cHYP], g1);
            g2 = fmaf(v, w2[c * cHYP], g2);
        }
    }
    const float* xr = cur + (size_t)b * curBs + (size_t)nn * cF;
    float x0 = xr[0], x1 = xr[1];
    float ps = sb[j] + x0 * sw[j] + x1 * sw[cHYP + j];
    float pt = tb[j] + x0 * tw[j] + x1 * tw[cHYP + j];
    ns[gid] = tanh_fast(kTAU * ps * g1);
    nt[gid] = tanh_fast(kTAU * pt * g2);
}

// adp rows (4 per block) -> combined coefficient (BE*adp + GA*adj) as tf32 hi/lo
__global__ __launch_bounds__(128) void k_adpcoef(
    const float* __restrict__ ns, const float* __restrict__ nt,
    const float* __restrict__ adj,
    uint32_t* __restrict__ coefHi, uint32_t* __restrict__ coefLo, int n)
{
    int b = blockIdx.y, i0 = blockIdx.x * 4;
    int tid = threadIdx.x;
    int lane = tid & 31, warp = tid >> 5;

    __shared__ float nsr[4][16], ntr[4][16];
    __shared__ float rowbuf[4][512];
    __shared__ float red[4][4];
    __shared__ float invs[4];

    if (tid < 64) {
        int ii = tid >> 4, c = tid & 15;
        nsr[ii][c] = ns[((size_t)b * n + i0 + ii) * 16 + c];
    } else {
        int t = tid - 64;
        int ii = t >> 4, c = t & 15;
        ntr[ii][c] = nt[((size_t)b * n + i0 + ii) * 16 + c];
    }
    __syncthreads();

    float lsum[4] = {0.f, 0.f, 0.f, 0.f};
    for (int m = tid; m < n; m += 128) {
        const float4* nsm = (const float4*)(ns + ((size_t)b * n + m) * 16);
        const float4* ntm = (const float4*)(nt + ((size_t)b * n + m) * 16);
        float4 s0 = nsm[0], s1 = nsm[1], s2 = nsm[2], s3 = nsm[3];
        float4 t0 = ntm[0], t1 = ntm[1], t2 = ntm[2], t3 = ntm[3];
        float sm[16] = {s0.x,s0.y,s0.z,s0.w, s1.x,s1.y,s1.z,s1.w,
                        s2.x,s2.y,s2.z,s2.w, s3.x,s3.y,s3.z,s3.w};
        float tm[16] = {t0.x,t0.y,t0.z,t0.w, t1.x,t1.y,t1.z,t1.w,
                        t2.x,t2.y,t2.z,t2.w, t3.x,t3.y,t3.z,t3.w};
#pragma unroll
        for (int ii = 0; ii < 4; ii++) {
            float a = 0.f;
#pragma unroll
            for (int c = 0; c < 16; c++)
                a += nsr[ii][c] * tm[c] - ntr[ii][c] * sm[c];
            float v = fmaxf(tanh_fast(kTAU * a), 0.f);
            if (m == i0 + ii) v += 1.f;
            rowbuf[ii][m] = v;
            lsum[ii] += v;
        }
    }
#pragma unroll
    for (int ii = 0; ii < 4; ii++) {
        float s = lsum[ii];
#pragma unroll
        for (int o = 16; o > 0; o >>= 1) s += __shfl_xor_sync(0xffffffffu, s, o);
        if (lane == 0) red[ii][warp] = s;
    }
    __syncthreads();
    if (tid < 4)
        invs[tid] = kBE / (red[tid][0] + red[tid][1] + red[tid][2] + red[tid][3]);
    __syncthreads();

    for (int m = tid; m < n; m += 128) {
#pragma unroll
        for (int ii = 0; ii < 4; ii++) {
            float v = rowbuf[ii][m] * invs[ii] + kGA * adj[(size_t)(i0 + ii) * n + m];
            size_t idx = ((size_t)b * n + i0 + ii) * n + m;
            uint32_t h = f2tf(v);
            coefHi[idx] = h;
            coefLo[idx] = f2tf(v - __uint_as_float(h));
        }
    }
}

// fused z & r gates; writes r*hidden into chainC slice0
__global__ void k_gate2(const float* __restrict__ chainZ, const float* __restrict__ chainS,
                        float* __restrict__ chainC,
                        const float* __restrict__ zw, const float* __restrict__ zbv,
                        const float* __restrict__ rw, const float* __restrict__ rbv,
                        float* __restrict__ zout, int n)
{
    int gid = blockIdx.x * blockDim.x + threadIdx.x;
    int total = cB * n * cH;
    if (gid >= total) return;
    int m = gid & (cH - 1);
    int row = gid >> 6;

    const float* ch = chainZ + (size_t)row * LDCH;
    float az = zbv[m], ar = rbv[m];
#pragma unroll
    for (int s = 0; s < 3; s++) {
        const float* cs = ch + s * CP;
        const float* wz = zw + (size_t)s * 66 * cH + m;
        const float* wr = rw + (size_t)s * 66 * cH + m;
#pragma unroll 6
        for (int c = 0; c < 66; c++) {
            float v = cs[c];
            az = fmaf(v, wz[c * cH], az);
            ar = fmaf(v, wr[c * cH], ar);
        }
    }
    float z = sigmoid_fast(az);
    float r = sigmoid_fast(ar);
    zout[gid] = z;
    chainC[(size_t)row * LDCH + cF + m] = r * chainS[(size_t)row * LDCH + m];
}

// fused c-gate + GRU hidden update; optionally packs next step inputs
__global__ void k_gcu(const float* __restrict__ chainC, float* __restrict__ chainS,
                      const float* __restrict__ zbuf,
                      const float* __restrict__ cw, const float* __restrict__ cbv,
                      const float* __restrict__ nextCur, size_t nextBs,
                      float* __restrict__ chainZ, float* __restrict__ chainCp, int n)
{
    int gid = blockIdx.x * blockDim.x + threadIdx.x;
    int total = cB * n * cH;
    if (gid >= total) return;
    int m = gid & (cH - 1);
    int row = gid >> 6;

    const float* ch = chainC + (size_t)row * LDCH;
    float ac = cbv[m];
#pragma unroll
    for (int s = 0; s < 3; s++) {
        const float* cs = ch + s * CP;
        const float* wc = cw + (size_t)s * 66 * cH + m;
#pragma unroll 6
        for (int c = 0; c < 66; c++)
            ac = fmaf(cs[c], wc[c * cH], ac);
    }
    float cval = tanh_fast(ac);
    float z = zbuf[gid];
    float* hp = chainS + (size_t)row * LDCH + m;
    float hnew = z * (*hp) + (1.f - z) * cval;
    *hp = hnew;
    if (nextCur) {
        chainZ[(size_t)row * LDCH + cF + m] = hnew;
        if (m < cF) {
            int nn = row % n, b = row / n;
            float x = nextCur[(size_t)b * nextBs + (size_t)nn * cF + m];
            chainZ[(size_t)row * LDCH + m]  = x;
            chainCp[(size_t)row * LDCH + m] = x;
        }
    }
}

// q/k projections for attention
__global__ void k_qk(const float* __restrict__ X,
                     const float* __restrict__ wqw, const float* __restrict__ wqb,
                     const float* __restrict__ wkw, const float* __restrict__ wkb,
                     float* __restrict__ q, float* __restrict__ kk, int n)
{
    int i = blockIdx.x * blockDim.x + threadIdx.x;
    int total = cB4 * n * cD;
    if (i >= total) return;
    int d = i % cD;
    int row = i / cD;
    int nn = row % n, bt = row / n;
    int b = bt >> 2, t = bt & 3;
    const float* xr = X + ((((size_t)b * cT) + (cT - 4) + t) * n + nn) * cF;
    kk[i] = wkb[d] + xr[0] * wkw[d] + xr[1] * wkw[cD + d];
    if (t == 3)
        q[((size_t)b * n + nn) * cD + d] = wqb[d] + xr[0] * wqw[d] + xr[1] * wqw[cD + d];
}

// scores + softmax + A_tgn = GA*(adj + attn); 4 rows i per block
__global__ __launch_bounds__(128) void k_attn(
    const float* __restrict__ q, const float* __restrict__ kk,
    const float* __restrict__ tw, const float* __restrict__ adj,
    float* __restrict__ Atgn, int n)
{
    int bt = blockIdx.y, i0 = blockIdx.x * 4;
    int b = bt >> 2;
    int tid = threadIdx.x;
    int lane = tid & 31, warp = tid >> 5;

    __shared__ float qd[4][8], twv[8];
    __shared__ float rowbuf[4][512];
    __shared__ float red[4][4];
    __shared__ float scal[4];

    if (tid < 32) {
        int ii = tid >> 3, d = tid & 7;
        qd[ii][d] = q[((size_t)b * n + i0 + ii) * 8 + d];
    } else if (tid < 40) {
        twv[tid - 32] = tw[tid - 32];
    }
    __syncthreads();

    float lmax[4] = {-1e30f, -1e30f, -1e30f, -1e30f};
    for (int j = tid; j < n; j += 128) {
        const float4* kj4 = (const float4*)(kk + ((size_t)bt * n + j) * 8);
        float4 k0 = kj4[0], k1 = kj4[1];
        float kj[8] = {k0.x,k0.y,k0.z,k0.w, k1.x,k1.y,k1.z,k1.w};
#pragma unroll
        for (int ii = 0; ii < 4; ii++) {
            float s = 0.f;
#pragma unroll
            for (int d = 0; d < 8; d++)
                s = fmaf(tanh_fast(qd[ii][d] + kj[d]), twv[d], s);
            rowbuf[ii][j] = s;
            lmax[ii] = fmaxf(lmax[ii], s);
        }
    }
#pragma unroll
    for (int ii = 0; ii < 4; ii++) {
        float s = lmax[ii];
#pragma unroll
        for (int o = 16; o > 0; o >>= 1) s = fmaxf(s, __shfl_xor_sync(0xffffffffu, s, o));
        if (lane == 0) red[ii][warp] = s;
    }
    __syncthreads();
    if (tid < 4)
        scal[tid] = fmaxf(fmaxf(red[tid][0], red[tid][1]), fmaxf(red[tid][2], red[tid][3]));
    __syncthreads();

    float lsum[4] = {0.f, 0.f, 0.f, 0.f};
    for (int j = tid; j < n; j += 128) {
#pragma unroll
        for (int ii = 0; ii < 4; ii++) {
            float e = __expf(rowbuf[ii][j] - scal[ii]);
            rowbuf[ii][j] = e;
            lsum[ii] += e;
        }
    }
#pragma unroll
    for (int ii = 0; ii < 4; ii++) {
        float s = lsum[ii];
#pragma unroll
        for (int o = 16; o > 0; o >>= 1) s += __shfl_xor_sync(0xffffffffu, s, o);
        if (lane == 0) red[ii][warp] = s;
    }
    __syncthreads();
    if (tid < 4)
        scal[tid] = 1.f / (red[tid][0] + red[tid][1] + red[tid][2] + red[tid][3]);
    __syncthreads();

    for (int j = tid; j < n; j += 128) {
#pragma unroll
        for (int ii = 0; ii < 4; ii++)
            Atgn[((size_t)bt * n + i0 + ii) * n + j] =
                kGA * (adj[(size_t)(i0 + ii) * n + j] + rowbuf[ii][j] * scal[ii]);
    }
}

__global__ void k_pack_tgn(const float* __restrict__ X, float* __restrict__ chainT, int n)
{
    int i = blockIdx.x * blockDim.x + threadIdx.x;
    int total = cB4 * n * cF;
    if (i >= total) return;
    int f = i % cF;
    int row = i / cF;
    int nn = row % n, bt = row / n;
    int b = bt >> 2, t = bt & 3;
    chainT[(size_t)row * 6 + f] =
        X[((((size_t)b * cT) + (cT - 4) + t) * n + nn) * cF + f];
}

// fused tgn matmul + relu + sum over t
__global__ void k_tgn_out(const float* __restrict__ chainT,
                          const float* __restrict__ tw, const float* __restrict__ tb,
                          float* __restrict__ tar2, int n)
{
    int gid = blockIdx.x * blockDim.x + threadIdx.x;
    int total = cB * n * cTGN;
    if (gid >= total) return;
    int m = gid & (cTGN - 1);
    int row = gid / cTGN;
    int nn = row % n, b = row / n;
    float tot = 0.f;
#pragma unroll
    for (int t = 0; t < 4; t++) {
        const float* cr = chainT + (((size_t)(b * 4 + t) * n) + nn) * 6;
        float s = tb[m];
#pragma unroll
        for (int k = 0; k < 6; k++)
            s = fmaf(cr[k], tw[k * cTGN + m], s);
        tot += fmaxf(s, 0.f);
    }
    tar2[gid] = tot;
}

// generic small FC: in1 (sliced) [+ in2 dense-ish]; mode 0 plain, 1 transposed store
__global__ void k_fc(const float* __restrict__ in1, int ld1, int sw1, int C1, int ns1,
                     const float* __restrict__ in2, int ld2, int C2,
                     const float* __restrict__ W, const float* __restrict__ Bv, int M,
                     float* __restrict__ out, int mode, int n, int rows)
{
    int gid = blockIdx.x * blockDim.x + threadIdx.x;
    if (gid >= rows * M) return;
    int m = gid % M;
    int row = gid / M;
    float acc = Bv[m];
    int k = 0;
    const float* r1 = in1 + (size_t)row * ld1;
    for (int s = 0; s < ns1; s++)
        for (int c = 0; c < C1; c++)
            acc = fmaf(r1[s * sw1 + c], W[(k++) * M + m], acc);
    if (in2) {
        const float* r2 = in2 + (size_t)row * ld2;
        for (int c = 0; c < C2; c++)
            acc = fmaf(r2[c], W[(k++) * M + m], acc);
    }
    if (mode == 0) out[(size_t)row * M + m] = acc;
    else {
        int nn = row % n, b = row / n;
        out[((size_t)b * M + m) * n + nn] = acc;
    }
}

// ---------------- host orchestration ----------------

struct Ptrs {
    float *chainS, *chainZ, *chainC, *ns, *nt, *z, *adjS;
    uint32_t *coefHi, *coefLo, *C1Hi, *C1Lo, *C2Hi, *C2Lo;
    float *Atgn, *q, *k, *chainT, *tar2, *gat;
};

// One GRU step. Assumes chainZ/chainC slice0 are already packed for this step.
// doDual=false skips the S-chain dual gconv (valid when hidden==0 and chainS
// slices 1,2 are already zero — the dual would write only zeros).
static void gru_step(bool doDual,
                     const float* cur, size_t curBs, const float* adj,
                     const float* a1w, const float* a1b, const float* a2w, const float* a2b,
                     const float* sw, const float* sb, const float* tw, const float* tb,
                     const float* zw, const float* zb, const float* rw, const float* rb,
                     const float* cw, const float* cb,
                     const float* nextCur, size_t nextBs, const Ptrs& P)
{
    const int n = cN;
    dim3 gg(DIV_UP(n, 32), cB);

    if (doDual)
        k_gconv2dual<<<gg, 192, GD_SMEM>>>(P.chainS, cH, P.C1Hi, P.C1Lo, P.C2Hi, P.C2Lo, n);

    k_agg<<<DIV_UP(cB * n * cHYP, 256), 256>>>(cur, curBs, P.chainS,
        a1w, a1b, a2w, a2b, sw, sb, tw, tb, P.ns, P.nt, n);

    k_adpcoef<<<dim3(n / 4, cB), 128>>>(P.ns, P.nt, adj, P.coefHi, P.coefLo, n);

    k_gconv2<<<gg, 192>>>(P.chainZ, cF + cH, 0, 1, P.coefHi, P.coefLo, (size_t)n * n, n);
    k_gconv2<<<gg, 192>>>(P.chainZ, cF + cH, 1, 2, P.coefHi, P.coefLo, (size_t)n * n, n);

    k_gate2<<<DIV_UP(cB * n * cH, 256), 256>>>(P.chainZ, P.chainS, P.chainC,
        zw, zb, rw, rb, P.z, n);

    k_gconv2<<<gg, 192>>>(P.chainC, cF + cH, 0, 1, P.coefHi, P.coefLo, (size_t)n * n, n);
    k_gconv2<<<gg, 192>>>(P.chainC, cF + cH, 1, 2, P.coefHi, P.coefLo, (size_t)n * n, n);

    k_gcu<<<DIV_UP(cB * n * cH, 256), 256>>>(P.chainC, P.chainS, P.z, cw, cb,
        nextCur, nextBs, P.chainZ, P.chainC, n);
}

extern "C" void kernel_launch(void* const* d_in, const int* in_sizes, int n_in,
                              void* d_out, int out_size)
{
    const float* X      = (const float*)d_in[0];
    const float* adj    = (const float*)d_in[1];
    const float* wq_w   = (const float*)d_in[7];
    const float* wq_b   = (const float*)d_in[8];
    const float* wk_w   = (const float*)d_in[9];
    const float* wk_b   = (const float*)d_in[10];
    const float* trans_w= (const float*)d_in[11];
    const float* tgn_w  = (const float*)d_in[12];
    const float* tgn_b  = (const float*)d_in[13];
    const float* agg1_w = (const float*)d_in[14];
    const float* agg1_b = (const float*)d_in[15];
    const float* agg2_w = (const float*)d_in[16];
    const float* agg2_b = (const float*)d_in[17];
    const float* src_w  = (const float*)d_in[18];
    const float* src_b  = (const float*)d_in[19];
    const float* tgt_w  = (const float*)d_in[20];
    const float* tgt_b  = (const float*)d_in[21];
    const float* gz_w   = (const float*)d_in[22];
    const float* gz_b   = (const float*)d_in[23];
    const float* gr_w   = (const float*)d_in[24];
    const float* gr_b   = (const float*)d_in[25];
    const float* gc_w   = (const float*)d_in[26];
    const float* gc_b   = (const float*)d_in[27];
    const float* fcs_w  = (const float*)d_in[28];
    const float* fcs_b  = (const float*)d_in[29];
    const float* fcm_w  = (const float*)d_in[30];
    const float* fcm_b  = (const float*)d_in[31];
    float* out = (float*)d_out;

    cudaFuncSetAttribute(k_gconv2dual, cudaFuncAttributeMaxDynamicSharedMemorySize, GD_SMEM);

    Ptrs P;
    cudaGetSymbolAddress((void**)&P.chainS, g_chainS);
    cudaGetSymbolAddress((void**)&P.chainZ, g_chainZ);
    cudaGetSymbolAddress((void**)&P.chainC, g_chainC);
    cudaGetSymbolAddress((void**)&P.coefHi, g_coefHi);
    cudaGetSymbolAddress((void**)&P.coefLo, g_coefLo);
    cudaGetSymbolAddress((void**)&P.adjS,   g_adjS);
    cudaGetSymbolAddress((void**)&P.C1Hi,   g_C1Hi);
    cudaGetSymbolAddress((void**)&P.C1Lo,   g_C1Lo);
    cudaGetSymbolAddress((void**)&P.C2Hi,   g_C2Hi);
    cudaGetSymbolAddress((void**)&P.C2Lo,   g_C2Lo);
    cudaGetSymbolAddress((void**)&P.ns,     g_ns);
    cudaGetSymbolAddress((void**)&P.nt,     g_nt);
    cudaGetSymbolAddress((void**)&P.z,      g_z);
    cudaGetSymbolAddress((void**)&P.Atgn,   g_Atgn);
    cudaGetSymbolAddress((void**)&P.q,      g_q);
    cudaGetSymbolAddress((void**)&P.k,      g_k);
    cudaGetSymbolAddress((void**)&P.chainT, g_chainT);
    cudaGetSymbolAddress((void**)&P.tar2,   g_tar2);
    cudaGetSymbolAddress((void**)&P.gat,    g_gat);

    const size_t Xbs = (size_t)cT * cN * cF;

    // ---- fork: attention branch on side stream (depends only on X, adj) ----
    cudaEventRecord(g_ss.fork, 0);
    cudaStreamWaitEvent(g_ss.s, g_ss.fork, 0);

    k_qk<<<DIV_UP(cB4 * cN * cD, 256), 256, 0, g_ss.s>>>(X, wq_w, wq_b, wk_w, wk_b, P.q, P.k, cN);
    k_attn<<<dim3(cN / 4, cB4), 128, 0, g_ss.s>>>(P.q, P.k, trans_w, adj, P.Atgn, cN);
    k_pack_tgn<<<DIV_UP(cB4 * cN * cF, 256), 256, 0, g_ss.s>>>(X, P.chainT, cN);
    dim3 ggt(DIV_UP(cN, 128), cB4);
    k_gconv_f2<<<ggt, 128, 0, g_ss.s>>>(P.chainT, 0, 1, P.Atgn, cN);
    k_gconv_f2<<<ggt, 128, 0, g_ss.s>>>(P.chainT, 1, 2, P.Atgn, cN);
    k_tgn_out<<<DIV_UP(cB * cN * cTGN, 256), 256, 0, g_ss.s>>>(P.chainT, tgn_w, tgn_b, P.tar2, cN);
    k_fc<<<DIV_UP(cB * cN * cF, 256), 256, 0, g_ss.s>>>(P.tar2, cTGN, 0, cTGN, 1,
        nullptr, 0, 0, fcs_w, fcs_b, cF, P.gat, 0, cN, cB * cN);

    cudaEventRecord(g_ss.join, g_ss.s);

    // ---- main branch: precompute S-chain matrices + GRU warmup ----
    k_adj2<<<dim3(DIV_UP(cN, 32), DIV_UP(cN, 32)), dim3(32, 32)>>>(adj, P.adjS, cN);
    k_coefhl2<<<DIV_UP(cN * cN, 256), 256>>>(adj, P.adjS,
        P.C1Hi, P.C1Lo, P.C2Hi, P.C2Lo, cN);

    // hidden (chainS) = 0 — deterministic per call (all 3 slices zeroed,
    // which also makes the step-0 dual gconv a skippable no-op)
    k_zero<<<DIV_UP(cB * cN * LDCH, 256), 256>>>(P.chainS, cB * cN * LDCH);

    // pack for step 0 (hidden = 0)
    k_pack<<<DIV_UP(cB * cN * CP, 256), 256>>>(X, Xbs, P.chainS, P.chainZ, P.chainC, cN);

    // warmup GRU steps: t = 0,4,8,12,16 (step 0 skips the dual — hidden is 0)
    for (int t = 0; t + 4 < cT; t += 4) {
        const float* nextCur = (t + 8 < cT) ? (X + (size_t)(t + 4) * cN * cF) : nullptr;
        gru_step(t != 0,
                 X + (size_t)t * cN * cF, Xbs, adj,
                 agg1_w, agg1_b, agg2_w, agg2_b, src_w, src_b, tgt_w, tgt_b,
                 gz_w, gz_b, gr_w, gr_b, gc_w, gc_b,
                 nextCur, Xbs, P);
    }

    // ---- join: gat/tar2 ready before the final step ----
    cudaStreamWaitEvent(0, g_ss.join, 0);

    // pack + final GRU step
    k_pack<<<DIV_UP(cB * cN * CP, 256), 256>>>(P.gat, (size_t)cN * cF, P.chainS,
        P.chainZ, P.chainC, cN);
    gru_step(true,
             P.gat, (size_t)cN * cF, adj,
             agg1_w, agg1_b, agg2_w, agg2_b, src_w, src_b, tgt_w, tgt_b,
             gz_w, gz_b, gr_w, gr_b, gc_w, gc_b,
             nullptr, 0, P);

    // out[b, l, n] = concat([tar2, hidden]) @ fcm_w + fcm_b (transposed store)
    k_fc<<<DIV_UP(cB * cN * cLEN, 256), 256>>>(P.tar2, cTGN, 0, cTGN, 1,
        P.chainS, LDCH, cH, fcm_w, fcm_b, cLEN, out, 1, cN, cB * cN);
}